// round 16
// baseline (speedup 1.0000x reference)
#include <cuda_runtime.h>
#include <cuda_fp16.h>
#include <cstdint>

#define BATCH 8
#define CCH   256
#define SPA   16384
#define HEADS 2
#define HK    128

// ---------------- scratch ----------------
__device__ float  g_bnp_s[256 * 4];
__device__ float  g_bnp_s2[256 * 4];
__device__ float  g_mean[CCH];
__device__ float  g_rstd[CCH];
__device__ __half g_wf_h[768 * 256];
__device__ float  g_bf[768];
__device__ uint32_t g_xh[BATCH * 128 * SPA];  // pair-packed fp16 x
__device__ __half g_k[BATCH * CCH * SPA];     // exp(k logits) fp16
__device__ __half g_q[BATCH * CCH * SPA];     // softmaxed q fp16
__device__ __half g_v[BATCH * CCH * SPA];
__device__ float  g_ctx_part[16 * 16 * 128 * 128];
__device__ float  g_context[16 * 128 * 128];
__device__ float  g_pooled_part[16 * 8];
__device__ float  g_gate[16];
__device__ float  g_kpart[128 * 2048];
__device__ float  g_kinv[2048];
__device__ __half g_M_h[BATCH * 256 * 256];
__device__ float  g_b2[256];

#define CTX_SCALE      16384.0f
#define CTX_UNSCALE    (1.0f / 16384.0f)

// ---------------- helpers ----------------
__device__ __forceinline__ uint32_t pk2(float lo, float hi) {
    uint32_t r;
    asm("cvt.rn.f16x2.f32 %0, %1, %2;" : "=r"(r) : "f"(hi), "f"(lo));
    return r;
}
__device__ __forceinline__ float2 h2f(uint32_t w) {
    __half2 h = *reinterpret_cast<__half2*>(&w);
    return __half22float2(h);
}
__device__ __forceinline__ uint32_t prmt(uint32_t a, uint32_t b, uint32_t sel) {
    uint32_t r;
    asm("prmt.b32 %0, %1, %2, %3;" : "=r"(r) : "r"(a), "r"(b), "r"(sel));
    return r;
}
__device__ __forceinline__ uint32_t hmul2(uint32_t a, uint32_t b) {
    uint32_t r;
    asm("mul.f16x2 %0, %1, %2;" : "=r"(r) : "r"(a), "r"(b));
    return r;
}

__device__ __forceinline__ void mma_f16(float c[4], const uint32_t a[4], const uint32_t b[2]) {
    asm volatile(
        "mma.sync.aligned.m16n8k16.row.col.f32.f16.f16.f32 "
        "{%0,%1,%2,%3}, {%4,%5,%6,%7}, {%8,%9}, {%0,%1,%2,%3};"
        : "+f"(c[0]), "+f"(c[1]), "+f"(c[2]), "+f"(c[3])
        : "r"(a[0]), "r"(a[1]), "r"(a[2]), "r"(a[3]), "r"(b[0]), "r"(b[1]));
}

#define AS_H 20
#define BS_H 136

// ======= 64x64-warp-tile compute =======
__device__ __forceinline__ void mma_block64(const uint32_t* __restrict__ As,
                                            const uint32_t* __restrict__ Bs,
                                            int mw, int nw, int g, int tig,
                                            float (&acc)[4][8][4]) {
#pragma unroll
    for (int ks2 = 0; ks2 < 16; ks2 += 8) {
        uint32_t a[4][4], bfr[8][2];
#pragma unroll
        for (int i = 0; i < 4; ++i) {
            const uint32_t* A0 = As + (mw + i * 16 + g) * AS_H + ks2;
            const uint32_t* A1 = A0 + 8 * AS_H;
            a[i][0] = A0[tig];     a[i][1] = A1[tig];
            a[i][2] = A0[tig + 4]; a[i][3] = A1[tig + 4];
        }
#pragma unroll
        for (int j = 0; j < 8; ++j) {
            int cb = nw + j * 8 + g;
            bfr[j][0] = Bs[(ks2 + tig) * BS_H + cb];
            bfr[j][1] = Bs[(ks2 + tig + 4) * BS_H + cb];
        }
#pragma unroll
        for (int i = 0; i < 4; ++i)
#pragma unroll
            for (int j = 0; j < 8; ++j)
                mma_f16(acc[i][j], a[i], bfr[j]);
    }
}

// 64x32 warp-tile compute (final)
__device__ __forceinline__ void mma_block16(const uint32_t* __restrict__ As,
                                            const uint32_t* __restrict__ Bs,
                                            int mw, int nw, int g, int tig,
                                            float (&acc)[4][4][4]) {
#pragma unroll
    for (int ks2 = 0; ks2 < 16; ks2 += 8) {
        uint32_t a[4][4], b[4][2];
#pragma unroll
        for (int i = 0; i < 4; ++i) {
            const uint32_t* A0 = As + (mw + i * 16 + g) * AS_H + ks2;
            const uint32_t* A1 = A0 + 8 * AS_H;
            a[i][0] = A0[tig];     a[i][1] = A1[tig];
            a[i][2] = A0[tig + 4]; a[i][3] = A1[tig + 4];
        }
#pragma unroll
        for (int j = 0; j < 4; ++j) {
            int cb = nw + j * 8 + g;
            b[j][0] = Bs[(ks2 + tig) * BS_H + cb];
            b[j][1] = Bs[(ks2 + tig + 4) * BS_H + cb];
        }
#pragma unroll
        for (int i = 0; i < 4; ++i)
#pragma unroll
            for (int j = 0; j < 4; ++j)
                mma_f16(acc[i][j], a[i], b[j]);
    }
}

// ---------------- K1a: BatchNorm stats + pair-packed fp16 copy ----------
__global__ void k_bnstats_part(const float* __restrict__ x) {
    const int ch = blockIdx.x;
    const int cp = blockIdx.y;
    const int tid = threadIdx.x;
    const int s0 = ch * 4096;
    const int c0 = cp * 2;
    float sA = 0.f, s2A = 0.f, sB = 0.f, s2B = 0.f;
    for (int b = 0; b < BATCH; ++b) {
        const float4* p0 = (const float4*)(x + ((size_t)(b * CCH + c0) << 14) + s0);
        const float4* p1 = (const float4*)(x + ((size_t)(b * CCH + c0 + 1) << 14) + s0);
        uint32_t* dst = g_xh + (((size_t)(b * 128 + cp)) << 14) + s0;
        for (int i = tid; i < 1024; i += 256) {
            float4 v0 = p0[i];
            float4 v1 = p1[i];
            sA  += v0.x + v0.y + v0.z + v0.w;
            s2A += v0.x * v0.x + v0.y * v0.y + v0.z * v0.z + v0.w * v0.w;
            sB  += v1.x + v1.y + v1.z + v1.w;
            s2B += v1.x * v1.x + v1.y * v1.y + v1.z * v1.z + v1.w * v1.w;
            uint4 t;
            t.x = pk2(v0.x, v1.x); t.y = pk2(v0.y, v1.y);
            t.z = pk2(v0.z, v1.z); t.w = pk2(v0.w, v1.w);
            *(uint4*)(dst + i * 4) = t;
        }
    }
    __shared__ float smA[256], sm2A[256], smB[256], sm2B[256];
    smA[tid] = sA; sm2A[tid] = s2A; smB[tid] = sB; sm2B[tid] = s2B;
    __syncthreads();
    for (int st = 128; st > 0; st >>= 1) {
        if (tid < st) {
            smA[tid] += smA[tid + st]; sm2A[tid] += sm2A[tid + st];
            smB[tid] += smB[tid + st]; sm2B[tid] += sm2B[tid + st];
        }
        __syncthreads();
    }
    if (tid == 0) {
        g_bnp_s [c0 * 4 + ch]       = smA[0];
        g_bnp_s2[c0 * 4 + ch]       = sm2A[0];
        g_bnp_s [(c0 + 1) * 4 + ch] = smB[0];
        g_bnp_s2[(c0 + 1) * 4 + ch] = sm2B[0];
    }
}

__global__ void k_bnstats_final() {
    int c = threadIdx.x;
    float s  = g_bnp_s [c * 4] + g_bnp_s [c * 4 + 1] + g_bnp_s [c * 4 + 2] + g_bnp_s [c * 4 + 3];
    float s2 = g_bnp_s2[c * 4] + g_bnp_s2[c * 4 + 1] + g_bnp_s2[c * 4 + 2] + g_bnp_s2[c * 4 + 3];
    const float inv_n = 1.f / (float)(BATCH * SPA);
    float mean = s * inv_n;
    float var  = s2 * inv_n - mean * mean;
    g_mean[c] = mean;
    g_rstd[c] = rsqrtf(var + 1e-5f);
}

// ---------------- K2: fold BN into kqv weights (fp16) ----------------
__global__ void k_fuseW(const float* __restrict__ wk, const float* __restrict__ bk,
                        const float* __restrict__ wq, const float* __restrict__ bq,
                        const float* __restrict__ wv, const float* __restrict__ bv,
                        const float* __restrict__ gamma, const float* __restrict__ beta) {
    int o = blockIdx.x * blockDim.x + threadIdx.x;
    if (o >= 768) return;
    const float* W; const float* bias; int r;
    if (o < 256)      { W = wk; bias = bk; r = o; }
    else if (o < 512) { W = wq; bias = bq; r = o - 256; }
    else              { W = wv; bias = bv; r = o - 512; }
    float bacc = bias[r];
    for (int c = 0; c < 256; ++c) {
        float a = g_rstd[c] * gamma[c];
        float d = beta[c] - g_mean[c] * a;
        float w = W[r * 256 + c];
        g_wf_h[o * 256 + c] = __float2half(w * a);
        bacc += w * d;
    }
    g_bf[o] = bacc;
}

// ---------------- K3: kqv GEMM — 128x128 tile, 4 warps, 2 CTAs/SM (R15) ------
__global__ __launch_bounds__(128, 2) void k_gemm_kqv() {
    __shared__ uint32_t smem[2][4736];
    const int tid = threadIdx.x;
    const int lane = tid & 31, wid = tid >> 5;
    const int g = lane >> 2, tig = lane & 3;
    const int mw = (wid & 1) * 64, nw = (wid >> 1) * 64;

    const int m0 = blockIdx.x << 7;
    const int by = blockIdx.y;
    const int b = by >> 7, s0 = (by & 127) << 7;
    const uint32_t* Bbase = g_xh + ((size_t)b * 128) * SPA;

    const int bkp = tid >> 4;
    const int bs = (tid & 15) * 8;

    uint4 pa[4], pb[4];
    float acc[4][8][4] = {};

#define KQV_LOAD(ks) do { \
    const uint4* ap = (const uint4*)(g_wf_h + (size_t)(m0 + tid) * 256 + (ks)); \
    pa[0] = ap[0]; pa[1] = ap[1]; pa[2] = ap[2]; pa[3] = ap[3]; \
    const uint32_t* br = Bbase + (size_t)(((ks) >> 1) + 2 * bkp) * SPA + s0 + bs; \
    pb[0] = *(const uint4*)br;        pb[1] = *(const uint4*)(br + 4); \
    pb[2] = *(const uint4*)(br + SPA); pb[3] = *(const uint4*)(br + SPA + 4); \
} while (0)

#define KQV_STAGE(buf) do { \
    uint32_t* dA = smem[buf] + tid * AS_H; \
    *(uint4*)(dA + 0)  = pa[0]; *(uint4*)(dA + 4)  = pa[1]; \
    *(uint4*)(dA + 8)  = pa[2]; *(uint4*)(dA + 12) = pa[3]; \
    uint32_t* dB = smem[buf] + 2560 + (2 * bkp) * BS_H + bs; \
    *(uint4*)(dB)            = pb[0]; *(uint4*)(dB + 4)        = pb[1]; \
    *(uint4*)(dB + BS_H)     = pb[2]; *(uint4*)(dB + BS_H + 4) = pb[3]; \
} while (0)

    KQV_LOAD(0);
    KQV_STAGE(0);
    KQV_LOAD(32);
    __syncthreads();

    for (int it = 0; it < 8; ++it) {
        const int cur = it & 1;
        if (it + 1 < 8) KQV_STAGE(cur ^ 1);
        if (it + 2 < 8) KQV_LOAD((it + 2) * 32);
        mma_block64(smem[cur], smem[cur] + 2560, mw, nw, g, tig, acc);
        __syncthreads();
    }

    // ---- epilogue (smem reuse) ----
    float* red  = (float*)smem;
    float* cmax = red + 2048;
    float* cinv = cmax + 128;

    if (m0 < 256) {
        const int slot = (wid >> 1) * 4 + tig;
#pragma unroll
        for (int i = 0; i < 4; ++i) {
            int r0 = mw + i * 16 + g;
            float b0 = g_bf[m0 + r0], b1 = g_bf[m0 + r0 + 8];
            float p0 = 0.f, p1 = 0.f;
#pragma unroll
            for (int j = 0; j < 8; ++j) {
                int col = s0 + nw + j * 8 + tig * 2;
                float e0 = __expf(acc[i][j][0] + b0), e1 = __expf(acc[i][j][1] + b0);
                float e2 = __expf(acc[i][j][2] + b1), e3 = __expf(acc[i][j][3] + b1);
                __half* o0 = g_k + (size_t)(b * CCH + m0 + r0) * SPA + col;
                *(uint32_t*)o0 = pk2(e0, e1);
                *(uint32_t*)(o0 + (size_t)8 * SPA) = pk2(e2, e3);
                p0 += e0 + e1;
                p1 += e2 + e3;
            }
            red[r0 * 8 + slot]       = p0;
            red[(r0 + 8) * 8 + slot] = p1;
        }
        __syncthreads();
        {
            float s = 0.f;
#pragma unroll
            for (int t = 0; t < 8; ++t) s += red[tid * 8 + t];
            g_kpart[(size_t)(by & 127) * 2048 + (b * 256 + m0 + tid)] = s;
        }
    } else if (m0 < 512) {
        const int rbase = m0 - 256;
        const int slotq = (wid & 1) * 8 + g;
#pragma unroll
        for (int j = 0; j < 8; ++j) {
            int cl = nw + j * 8 + tig * 2;
            float mA = -1e30f, mB = -1e30f;
#pragma unroll
            for (int i = 0; i < 4; ++i) {
                float b0 = g_bf[m0 + mw + i * 16 + g];
                float b1 = g_bf[m0 + mw + i * 16 + g + 8];
                mA = fmaxf(mA, fmaxf(acc[i][j][0] + b0, acc[i][j][2] + b1));
                mB = fmaxf(mB, fmaxf(acc[i][j][1] + b0, acc[i][j][3] + b1));
            }
            red[cl * 16 + slotq]       = mA;
            red[(cl + 1) * 16 + slotq] = mB;
        }
        __syncthreads();
        {
            float m = -1e30f;
#pragma unroll
            for (int t = 0; t < 16; ++t) m = fmaxf(m, red[tid * 16 + t]);
            cmax[tid] = m;
        }
        __syncthreads();
#pragma unroll
        for (int j = 0; j < 8; ++j) {
            int cl = nw + j * 8 + tig * 2;
            float cmA = cmax[cl], cmB = cmax[cl + 1];
            float sA = 0.f, sB = 0.f;
#pragma unroll
            for (int i = 0; i < 4; ++i) {
                float b0 = g_bf[m0 + mw + i * 16 + g];
                float b1 = g_bf[m0 + mw + i * 16 + g + 8];
                sA += __expf(acc[i][j][0] + b0 - cmA) + __expf(acc[i][j][2] + b1 - cmA);
                sB += __expf(acc[i][j][1] + b0 - cmB) + __expf(acc[i][j][3] + b1 - cmB);
            }
            red[cl * 16 + slotq]       = sA;
            red[(cl + 1) * 16 + slotq] = sB;
        }
        __syncthreads();
        {
            float s = 0.f;
#pragma unroll
            for (int t = 0; t < 16; ++t) s += red[tid * 16 + t];
            cinv[tid] = 1.f / s;
        }
        __syncthreads();
#pragma unroll
        for (int i = 0; i < 4; ++i) {
            int r0 = mw + i * 16 + g;
            float b0 = g_bf[m0 + r0], b1 = g_bf[m0 + r0 + 8];
#pragma unroll
            for (int j = 0; j < 8; ++j) {
                int cl = nw + j * 8 + tig * 2;
                float cmA = cmax[cl], cmB = cmax[cl + 1];
                float ciA = cinv[cl], ciB = cinv[cl + 1];
                int col = s0 + cl;
                __half* o0 = g_q + (size_t)(b * CCH + rbase + r0) * SPA + col;
                *(uint32_t*)o0 = pk2(__expf(acc[i][j][0] + b0 - cmA) * ciA,
                                     __expf(acc[i][j][1] + b0 - cmB) * ciB);
                *(uint32_t*)(o0 + (size_t)8 * SPA) =
                    pk2(__expf(acc[i][j][2] + b1 - cmA) * ciA,
                        __expf(acc[i][j][3] + b1 - cmB) * ciB);
            }
        }
    } else {
        const int rbase = m0 - 512;
#pragma unroll
        for (int i = 0; i < 4; ++i) {
            int r0 = mw + i * 16 + g;
            float b0 = g_bf[m0 + r0], b1 = g_bf[m0 + r0 + 8];
#pragma unroll
            for (int j = 0; j < 8; ++j) {
                int col = s0 + nw + j * 8 + tig * 2;
                __half* o0 = g_v + (size_t)(b * CCH + rbase + r0) * SPA + col;
                *(uint32_t*)o0 = pk2(acc[i][j][0] + b0, acc[i][j][1] + b0);
                *(uint32_t*)(o0 + (size_t)8 * SPA) = pk2(acc[i][j][2] + b1, acc[i][j][3] + b1);
            }
        }
    }
}

// ---------------- K4: reduce k partial sums -> 1/sum ----------------
__global__ void k_ksum() {
    int row = blockIdx.x * 256 + threadIdx.x;
    float s = 0.f;
    for (int st = 0; st < 128; ++st) s += g_kpart[(size_t)st * 2048 + row];
    g_kinv[row] = 1.f / s;
}

// ---------------- K6: context — 128x128 tile, 4 warps (64x64), 2 CTAs/SM ------
__global__ __launch_bounds__(128, 2) void k_context() {
    __shared__ uint32_t smem[2][4736];   // As(2560) + Bs(2176)
    const int tid = threadIdx.x;
    const int lane = tid & 31, wid = tid >> 5;
    const int g = lane >> 2, tig = lane & 3;
    const int mw = (wid & 1) * 64, nw = (wid >> 1) * 64;

    const int split = blockIdx.x;
    const int bn = blockIdx.y;
    const __half* Kb = g_k + ((size_t)bn * HK) * SPA;   // exp(k)
    const __half* Vb = g_v + ((size_t)bn * HK) * SPA;
    const int sb0 = split * 1024;

    const float kivs = g_kinv[bn * HK + tid] * CTX_SCALE;
    const uint32_t kiv2 = pk2(kivs, kivs);

    uint4 ra[4], rb[4];
    float acc[4][8][4] = {};

#define CTX_LOAD(ks) do { \
    const uint4* ksrc = (const uint4*)(Kb + (size_t)tid * SPA + (ks)); \
    ra[0] = ksrc[0]; ra[1] = ksrc[1]; ra[2] = ksrc[2]; ra[3] = ksrc[3]; \
    const uint4* vsrc = (const uint4*)(Vb + (size_t)tid * SPA + (ks)); \
    rb[0] = vsrc[0]; rb[1] = vsrc[1]; rb[2] = vsrc[2]; rb[3] = vsrc[3]; \
} while (0)

#define CTX_STAGE(buf) do { \
    uint32_t* dA = smem[buf] + tid * AS_H; \
    const uint32_t* wa = (const uint32_t*)ra; \
    _Pragma("unroll") \
    for (int p = 0; p < 16; ++p) dA[p] = hmul2(wa[p], kiv2); \
    uint32_t* BB = smem[buf] + 2560; \
    const uint32_t* wb = (const uint32_t*)rb; \
    _Pragma("unroll") \
    for (int p = 0; p < 16; ++p) BB[p * BS_H + tid] = wb[p]; \
} while (0)

    CTX_LOAD(sb0);
    CTX_STAGE(0);
    CTX_LOAD(sb0 + 32);
    __syncthreads();

    for (int it = 0; it < 32; ++it) {
        const int cur = it & 1;
        if (it + 1 < 32) CTX_STAGE(cur ^ 1);
        if (it + 2 < 32) CTX_LOAD(sb0 + (it + 2) * 32);
        mma_block64(smem[cur], smem[cur] + 2560, mw, nw, g, tig, acc);
        __syncthreads();
    }

    float* outp = g_ctx_part + ((size_t)(bn * 16 + split)) * 16384;
#pragma unroll
    for (int i = 0; i < 4; ++i) {
        int row0 = mw + i * 16 + g;
#pragma unroll
        for (int j = 0; j < 8; ++j) {
            int col = nw + j * 8 + tig * 2;
            float* o0 = outp + row0 * 128 + col;
            float* o1 = o0 + 8 * 128;
            *(float2*)o0 = make_float2(acc[i][j][0] * CTX_UNSCALE, acc[i][j][1] * CTX_UNSCALE);
            *(float2*)o1 = make_float2(acc[i][j][2] * CTX_UNSCALE, acc[i][j][3] * CTX_UNSCALE);
        }
    }
}

// ---------------- K7: reduce partials + pooled partials ----------------
__global__ void k_reduce_ctx() {
    const int ch = blockIdx.x;
    const int bn = blockIdx.y;
    const int tid = threadIdx.x;
    const int e0 = ch * 2048;
    float acc = 0.f;
    for (int e = e0 + tid; e < e0 + 2048; e += 256) {
        float s = 0.f;
#pragma unroll
        for (int p = 0; p < 16; ++p)
            s += g_ctx_part[((size_t)(bn * 16 + p)) * 16384 + e];
        g_context[((size_t)bn << 14) + e] = s;
        acc += s;
    }
    __shared__ float sm[256];
    sm[tid] = acc; __syncthreads();
    for (int st = 128; st > 0; st >>= 1) {
        if (tid < st) sm[tid] += sm[tid + st];
        __syncthreads();
    }
    if (tid == 0) g_pooled_part[bn * 8 + ch] = sm[0];
}

// ---------------- K8: SE gate ----------------
__global__ void k_gate(const float* __restrict__ w_fc1, const float* __restrict__ b_fc1,
                       const float* __restrict__ w_fc2, const float* __restrict__ b_fc2) {
    int b = threadIdx.x;
    if (b >= BATCH) return;
    float p0 = 0.f, p1 = 0.f;
#pragma unroll
    for (int ch = 0; ch < 8; ++ch) {
        p0 += g_pooled_part[(b * 2) * 8 + ch];
        p1 += g_pooled_part[(b * 2 + 1) * 8 + ch];
    }
    p0 *= (1.f / 16384.f);
    p1 *= (1.f / 16384.f);
    float h0 = fmaxf(0.f, p0 * w_fc1[0] + p1 * w_fc1[1] + b_fc1[0]);
    float h1 = fmaxf(0.f, p0 * w_fc1[2] + p1 * w_fc1[3] + b_fc1[1]);
    float z0 = h0 * w_fc2[0] + h1 * w_fc2[1] + b_fc2[0];
    float z1 = h0 * w_fc2[2] + h1 * w_fc2[3] + b_fc2[1];
    g_gate[b * 2]     = 1.f / (1.f + __expf(-z0));
    g_gate[b * 2 + 1] = 1.f / (1.f + __expf(-z1));
}

// ---------------- K10: M_b = w_rep-slices @ (gated combined ctx_b), fp16 out ----
__global__ __launch_bounds__(256) void k_mkM(const float* __restrict__ w_rep,
                                             const float* __restrict__ w_se) {
    __shared__ float Ws[64][65];
    __shared__ float Cs[64][65];
    const int bid = blockIdx.x;
    const int b = bid >> 4;
    const int rem = bid & 15;
    const int ot = rem >> 2, kt = rem & 3;
    const int n = kt >> 1;
    const int kc0 = (kt & 1) << 6;
    const int o0 = ot << 6;
    const int tid = threadIdx.x;
    const int tx = tid & 15, ty = tid >> 4;
    const float* ctx0 = g_context + ((size_t)(b * 2) << 14);
    const float* ctx1 = g_context + ((size_t)(b * 2 + 1) << 14);
    const float wg0 = w_se[0] * g_gate[b * 2];
    const float wg1 = w_se[1] * g_gate[b * 2 + 1];
    float acc[4][4] = {};
    const int lrow = tid >> 2;
    const int lc0 = (tid & 3) << 4;
    for (int h = 0; h < 2; ++h) {
        const int vb = n * 128 + h * 64;
#pragma unroll
        for (int f = 0; f < 4; ++f) {
            float4 wv = *(const float4*)(w_rep + (o0 + lrow) * 256 + vb + lc0 + f * 4);
            Ws[lrow][lc0 + f * 4 + 0] = wv.x; Ws[lrow][lc0 + f * 4 + 1] = wv.y;
            Ws[lrow][lc0 + f * 4 + 2] = wv.z; Ws[lrow][lc0 + f * 4 + 3] = wv.w;
            int cidx = (kc0 + lrow) * 128 + h * 64 + lc0 + f * 4;
            float4 c0 = *(const float4*)(ctx0 + cidx);
            float4 c1 = *(const float4*)(ctx1 + cidx);
            Cs[lrow][lc0 + f * 4 + 0] = wg0 * c0.x + wg1 * c1.x;
            Cs[lrow][lc0 + f * 4 + 1] = wg0 * c0.y + wg1 * c1.y;
            Cs[lrow][lc0 + f * 4 + 2] = wg0 * c0.z + wg1 * c1.z;
            Cs[lrow][lc0 + f * 4 + 3] = wg0 * c0.w + wg1 * c1.w;
        }
        __syncthreads();
        for (int vl = 0; vl < 64; ++vl) {
            float a[4], bb[4];
#pragma unroll
            for (int i = 0; i < 4; ++i) a[i]  = Ws[ty * 4 + i][vl];
#pragma unroll
            for (int j = 0; j < 4; ++j) bb[j] = Cs[tx * 4 + j][vl];
#pragma unroll
            for (int i = 0; i < 4; ++i)
#pragma unroll
                for (int j = 0; j < 4; ++j) acc[i][j] += a[i] * bb[j];
        }
        __syncthreads();
    }
#pragma unroll
    for (int i = 0; i < 4; ++i)
#pragma unroll
        for (int j = 0; j < 4; ++j)
            g_M_h[(size_t)b * 65536 + (o0 + ty * 4 + i) * 256 + kt * 64 + tx * 4 + j] =
                __float2half(acc[i][j]);
}

// ---------------- K11: b2 bias fold ----------------
__global__ void k_bias2(const float* __restrict__ w_rep, const float* __restrict__ b_rep,
                        const float* __restrict__ b_se) {
    int o = threadIdx.x;
    float s = 0.f;
    for (int c = 0; c < 256; ++c) s += w_rep[o * 256 + c];
    g_b2[o] = b_rep[o] + b_se[0] * s;
}

// ---------------- K12: final GEMM (R12 proven) ----------------
__global__ __launch_bounds__(256) void k_final_fused(float* __restrict__ out) {
    __shared__ uint32_t As[2][128 * AS_H];
    __shared__ uint32_t Bs[2][16 * BS_H];
    const int tid = threadIdx.x;
    const int lane = tid & 31, wid = tid >> 5;
    const int g = lane >> 2, tig = lane & 3;
    const int mw = (wid & 1) * 64, nw = (wid >> 1) * 32;

    const int m0 = blockIdx.x << 7;
    const int by = blockIdx.y;
    const int b = by >> 7, s0 = (by & 127) << 7;
    const __half* Am = g_M_h + (size_t)b * 65536;
    const __half* Bq = g_q + (size_t)b * CCH * SPA;

    const int ar = tid >> 1, ak = (tid & 1) * 16;
    const int bkp = tid >> 4, bs = (tid & 15) * 8;

    uint4 pa0, pa1, rb0, rb1;
    float acc[4][4][4] = {};

#define FIN_LOAD(ks) do { \
    const uint4* ap = (const uint4*)(Am + (size_t)(m0 + ar) * 256 + (ks) + ak); \
    pa0 = ap[0]; pa1 = ap[1]; \
    const __half* q0_ = Bq + (size_t)((ks) + 2 * bkp) * SPA + s0 + bs; \
    rb0 = *(const uint4*)q0_; \
    rb1 = *(const uint4*)(q0_ + SPA); \
} while (0)

#define FIN_STAGE(buf) do { \
    uint32_t* dA = As[buf] + ar * AS_H + (ak >> 1); \
    *(uint4*)(dA + 0) = pa0; *(uint4*)(dA + 4) = pa1; \
    const uint32_t* w0 = (const uint32_t*)&rb0; \
    const uint32_t* w1 = (const uint32_t*)&rb1; \
    uint32_t* dB = Bs[buf] + bkp * BS_H + bs; \
    _Pragma("unroll") \
    for (int q = 0; q < 4; ++q) { \
        dB[2 * q]     = prmt(w0[q], w1[q], 0x5410); \
        dB[2 * q + 1] = prmt(w0[q], w1[q], 0x7632); \
    } \
} while (0)

    FIN_LOAD(0);
    FIN_STAGE(0);
    FIN_LOAD(32);
    __syncthreads();

    for (int it = 0; it < 8; ++it) {
        const int cur = it & 1;
        if (it + 1 < 8) FIN_STAGE(cur ^ 1);
        if (it + 2 < 8) FIN_LOAD((it + 2) * 32);
        mma_block16(As[cur], Bs[cur], mw, nw, g, tig, acc);
        __syncthreads();
    }

#pragma unroll
    for (int i = 0; i < 4; ++i) {
        int row0 = m0 + mw + i * 16 + g;
        float bias0 = g_b2[row0];
        float bias1 = g_b2[row0 + 8];
#pragma unroll
        for (int j = 0; j < 4; ++j) {
            int col = s0 + nw + j * 8 + tig * 2;
            float* o0 = out + (size_t)(b * CCH + row0) * SPA + col;
            float* o1 = o0 + (size_t)8 * SPA;
            *(float2*)o0 = make_float2(acc[i][j][0] + bias0, acc[i][j][1] + bias0);
            *(float2*)o1 = make_float2(acc[i][j][2] + bias1, acc[i][j][3] + bias1);
        }
    }
}

// ---------------- launch ----------------
extern "C" void kernel_launch(void* const* d_in, const int* in_sizes, int n_in,
                              void* d_out, int out_size) {
    const float* x     = (const float*)d_in[0];
    const float* gamma = (const float*)d_in[1];
    const float* beta  = (const float*)d_in[2];
    const float* wk    = (const float*)d_in[3];
    const float* bk    = (const float*)d_in[4];
    const float* wq    = (const float*)d_in[5];
    const float* bq    = (const float*)d_in[6];
    const float* wv    = (const float*)d_in[7];
    const float* bv    = (const float*)d_in[8];
    const float* w_fc1 = (const float*)d_in[9];
    const float* b_fc1 = (const float*)d_in[10];
    const float* w_fc2 = (const float*)d_in[11];
    const float* b_fc2 = (const float*)d_in[12];
    const float* w_se  = (const float*)d_in[13];
    const float* b_se  = (const float*)d_in[14];
    const float* w_rep = (const float*)d_in[15];
    const float* b_rep = (const float*)d_in[16];
    float* out = (float*)d_out;

    k_bnstats_part<<<dim3(4, 128), 256>>>(x);
    k_bnstats_final<<<1, 256>>>();
    k_fuseW<<<3, 256>>>(wk, bk, wq, bq, wv, bv, gamma, beta);
    k_gemm_kqv<<<dim3(6, 1024), 128>>>();
    k_ksum<<<8, 256>>>();
    k_context<<<dim3(16, 16), 128>>>();
    k_reduce_ctx<<<dim3(8, 16), 256>>>();
    k_gate<<<1, 32>>>(w_fc1, b_fc1, w_fc2, b_fc2);
    k_mkM<<<128, 256>>>(w_rep, w_se);
    k_bias2<<<1, 256>>>(w_rep, b_rep, b_se);
    k_final_fused<<<dim3(2, 1024), 256>>>(out);
}

// round 17
// speedup vs baseline: 1.0196x; 1.0196x over previous
#include <cuda_runtime.h>
#include <cuda_fp16.h>
#include <cstdint>

#define BATCH 8
#define CCH   256
#define SPA   16384
#define HEADS 2
#define HK    128

// ---------------- scratch ----------------
__device__ float  g_bnp_s[256 * 8];
__device__ float  g_bnp_s2[256 * 8];
__device__ float  g_mean[CCH];
__device__ float  g_rstd[CCH];
__device__ __half g_wf_h[768 * 256];
__device__ float  g_bf[768];
__device__ uint32_t g_xh[BATCH * 128 * SPA];  // pair-packed fp16 x
__device__ __half g_k[BATCH * CCH * SPA];     // exp(k logits) fp16
__device__ __half g_q[BATCH * CCH * SPA];     // softmaxed q fp16
__device__ __half g_v[BATCH * CCH * SPA];
__device__ float  g_ctx_part[16 * 16 * 128 * 128];
__device__ float  g_context[16 * 128 * 128];
__device__ float  g_pooled_part[16 * 8];
__device__ float  g_gate[16];
__device__ float  g_kpart[128 * 2048];
__device__ float  g_kinv[2048];
__device__ __half g_M_h[BATCH * 256 * 256];
__device__ float  g_b2[256];

#define CTX_SCALE      16384.0f
#define CTX_UNSCALE    (1.0f / 16384.0f)

// ---------------- helpers ----------------
__device__ __forceinline__ uint32_t pk2(float lo, float hi) {
    uint32_t r;
    asm("cvt.rn.f16x2.f32 %0, %1, %2;" : "=r"(r) : "f"(hi), "f"(lo));
    return r;
}
__device__ __forceinline__ float2 h2f(uint32_t w) {
    __half2 h = *reinterpret_cast<__half2*>(&w);
    return __half22float2(h);
}
__device__ __forceinline__ uint32_t prmt(uint32_t a, uint32_t b, uint32_t sel) {
    uint32_t r;
    asm("prmt.b32 %0, %1, %2, %3;" : "=r"(r) : "r"(a), "r"(b), "r"(sel));
    return r;
}
__device__ __forceinline__ uint32_t hmul2(uint32_t a, uint32_t b) {
    uint32_t r;
    asm("mul.f16x2 %0, %1, %2;" : "=r"(r) : "r"(a), "r"(b));
    return r;
}

__device__ __forceinline__ void mma_f16(float c[4], const uint32_t a[4], const uint32_t b[2]) {
    asm volatile(
        "mma.sync.aligned.m16n8k16.row.col.f32.f16.f16.f32 "
        "{%0,%1,%2,%3}, {%4,%5,%6,%7}, {%8,%9}, {%0,%1,%2,%3};"
        : "+f"(c[0]), "+f"(c[1]), "+f"(c[2]), "+f"(c[3])
        : "r"(a[0]), "r"(a[1]), "r"(a[2]), "r"(a[3]), "r"(b[0]), "r"(b[1]));
}

#define AS_H 20
#define BS_H 136

// ======= 64x64-warp-tile compute (kqv) =======
__device__ __forceinline__ void mma_block64(const uint32_t* __restrict__ As,
                                            const uint32_t* __restrict__ Bs,
                                            int mw, int nw, int g, int tig,
                                            float (&acc)[4][8][4]) {
#pragma unroll
    for (int ks2 = 0; ks2 < 16; ks2 += 8) {
        uint32_t a[4][4], bfr[8][2];
#pragma unroll
        for (int i = 0; i < 4; ++i) {
            const uint32_t* A0 = As + (mw + i * 16 + g) * AS_H + ks2;
            const uint32_t* A1 = A0 + 8 * AS_H;
            a[i][0] = A0[tig];     a[i][1] = A1[tig];
            a[i][2] = A0[tig + 4]; a[i][3] = A1[tig + 4];
        }
#pragma unroll
        for (int j = 0; j < 8; ++j) {
            int cb = nw + j * 8 + g;
            bfr[j][0] = Bs[(ks2 + tig) * BS_H + cb];
            bfr[j][1] = Bs[(ks2 + tig + 4) * BS_H + cb];
        }
#pragma unroll
        for (int i = 0; i < 4; ++i)
#pragma unroll
            for (int j = 0; j < 8; ++j)
                mma_f16(acc[i][j], a[i], bfr[j]);
    }
}

// 64x32 warp-tile compute (context / final)
__device__ __forceinline__ void mma_block16(const uint32_t* __restrict__ As,
                                            const uint32_t* __restrict__ Bs,
                                            int mw, int nw, int g, int tig,
                                            float (&acc)[4][4][4]) {
#pragma unroll
    for (int ks2 = 0; ks2 < 16; ks2 += 8) {
        uint32_t a[4][4], b[4][2];
#pragma unroll
        for (int i = 0; i < 4; ++i) {
            const uint32_t* A0 = As + (mw + i * 16 + g) * AS_H + ks2;
            const uint32_t* A1 = A0 + 8 * AS_H;
            a[i][0] = A0[tig];     a[i][1] = A1[tig];
            a[i][2] = A0[tig + 4]; a[i][3] = A1[tig + 4];
        }
#pragma unroll
        for (int j = 0; j < 4; ++j) {
            int cb = nw + j * 8 + g;
            b[j][0] = Bs[(ks2 + tig) * BS_H + cb];
            b[j][1] = Bs[(ks2 + tig + 4) * BS_H + cb];
        }
#pragma unroll
        for (int i = 0; i < 4; ++i)
#pragma unroll
            for (int j = 0; j < 4; ++j)
                mma_f16(acc[i][j], a[i], b[j]);
    }
}

// ---------------- K1a: BatchNorm stats + pair-packed fp16 copy (8 chunks) -----
__global__ void k_bnstats_part(const float* __restrict__ x) {
    const int ch = blockIdx.x;          // 0..7 spatial chunk
    const int cp = blockIdx.y;          // 0..127 channel pair
    const int tid = threadIdx.x;
    const int s0 = ch * 2048;
    const int c0 = cp * 2;
    float sA = 0.f, s2A = 0.f, sB = 0.f, s2B = 0.f;
    for (int b = 0; b < BATCH; ++b) {
        const float4* p0 = (const float4*)(x + ((size_t)(b * CCH + c0) << 14) + s0);
        const float4* p1 = (const float4*)(x + ((size_t)(b * CCH + c0 + 1) << 14) + s0);
        uint32_t* dst = g_xh + (((size_t)(b * 128 + cp)) << 14) + s0;
        for (int i = tid; i < 512; i += 256) {
            float4 v0 = p0[i];
            float4 v1 = p1[i];
            sA  += v0.x + v0.y + v0.z + v0.w;
            s2A += v0.x * v0.x + v0.y * v0.y + v0.z * v0.z + v0.w * v0.w;
            sB  += v1.x + v1.y + v1.z + v1.w;
            s2B += v1.x * v1.x + v1.y * v1.y + v1.z * v1.z + v1.w * v1.w;
            uint4 t;
            t.x = pk2(v0.x, v1.x); t.y = pk2(v0.y, v1.y);
            t.z = pk2(v0.z, v1.z); t.w = pk2(v0.w, v1.w);
            *(uint4*)(dst + i * 4) = t;
        }
    }
    __shared__ float smA[256], sm2A[256], smB[256], sm2B[256];
    smA[tid] = sA; sm2A[tid] = s2A; smB[tid] = sB; sm2B[tid] = s2B;
    __syncthreads();
    for (int st = 128; st > 0; st >>= 1) {
        if (tid < st) {
            smA[tid] += smA[tid + st]; sm2A[tid] += sm2A[tid + st];
            smB[tid] += smB[tid + st]; sm2B[tid] += sm2B[tid + st];
        }
        __syncthreads();
    }
    if (tid == 0) {
        g_bnp_s [c0 * 8 + ch]       = smA[0];
        g_bnp_s2[c0 * 8 + ch]       = sm2A[0];
        g_bnp_s [(c0 + 1) * 8 + ch] = smB[0];
        g_bnp_s2[(c0 + 1) * 8 + ch] = sm2B[0];
    }
}

__global__ void k_bnstats_final() {
    int c = threadIdx.x;
    float s = 0.f, s2 = 0.f;
#pragma unroll
    for (int ch = 0; ch < 8; ++ch) {
        s  += g_bnp_s [c * 8 + ch];
        s2 += g_bnp_s2[c * 8 + ch];
    }
    const float inv_n = 1.f / (float)(BATCH * SPA);
    float mean = s * inv_n;
    float var  = s2 * inv_n - mean * mean;
    g_mean[c] = mean;
    g_rstd[c] = rsqrtf(var + 1e-5f);
}

// ---------------- K2: fold BN into kqv weights (fp16) ----------------
__global__ void k_fuseW(const float* __restrict__ wk, const float* __restrict__ bk,
                        const float* __restrict__ wq, const float* __restrict__ bq,
                        const float* __restrict__ wv, const float* __restrict__ bv,
                        const float* __restrict__ gamma, const float* __restrict__ beta) {
    int o = blockIdx.x * blockDim.x + threadIdx.x;
    if (o >= 768) return;
    const float* W; const float* bias; int r;
    if (o < 256)      { W = wk; bias = bk; r = o; }
    else if (o < 512) { W = wq; bias = bq; r = o - 256; }
    else              { W = wv; bias = bv; r = o - 512; }
    float bacc = bias[r];
    for (int c = 0; c < 256; ++c) {
        float a = g_rstd[c] * gamma[c];
        float d = beta[c] - g_mean[c] * a;
        float w = W[r * 256 + c];
        g_wf_h[o * 256 + c] = __float2half(w * a);
        bacc += w * d;
    }
    g_bf[o] = bacc;
}

// ---------------- K3: kqv GEMM — 128x128 tile, 4 warps, 2 CTAs/SM (R15) ------
__global__ __launch_bounds__(128, 2) void k_gemm_kqv() {
    __shared__ uint32_t smem[2][4736];
    const int tid = threadIdx.x;
    const int lane = tid & 31, wid = tid >> 5;
    const int g = lane >> 2, tig = lane & 3;
    const int mw = (wid & 1) * 64, nw = (wid >> 1) * 64;

    const int m0 = blockIdx.x << 7;
    const int by = blockIdx.y;
    const int b = by >> 7, s0 = (by & 127) << 7;
    const uint32_t* Bbase = g_xh + ((size_t)b * 128) * SPA;

    const int bkp = tid >> 4;
    const int bs = (tid & 15) * 8;

    uint4 pa[4], pb[4];
    float acc[4][8][4] = {};

#define KQV_LOAD(ks) do { \
    const uint4* ap = (const uint4*)(g_wf_h + (size_t)(m0 + tid) * 256 + (ks)); \
    pa[0] = ap[0]; pa[1] = ap[1]; pa[2] = ap[2]; pa[3] = ap[3]; \
    const uint32_t* br = Bbase + (size_t)(((ks) >> 1) + 2 * bkp) * SPA + s0 + bs; \
    pb[0] = *(const uint4*)br;        pb[1] = *(const uint4*)(br + 4); \
    pb[2] = *(const uint4*)(br + SPA); pb[3] = *(const uint4*)(br + SPA + 4); \
} while (0)

#define KQV_STAGE(buf) do { \
    uint32_t* dA = smem[buf] + tid * AS_H; \
    *(uint4*)(dA + 0)  = pa[0]; *(uint4*)(dA + 4)  = pa[1]; \
    *(uint4*)(dA + 8)  = pa[2]; *(uint4*)(dA + 12) = pa[3]; \
    uint32_t* dB = smem[buf] + 2560 + (2 * bkp) * BS_H + bs; \
    *(uint4*)(dB)            = pb[0]; *(uint4*)(dB + 4)        = pb[1]; \
    *(uint4*)(dB + BS_H)     = pb[2]; *(uint4*)(dB + BS_H + 4) = pb[3]; \
} while (0)

    KQV_LOAD(0);
    KQV_STAGE(0);
    KQV_LOAD(32);
    __syncthreads();

    for (int it = 0; it < 8; ++it) {
        const int cur = it & 1;
        if (it + 1 < 8) KQV_STAGE(cur ^ 1);
        if (it + 2 < 8) KQV_LOAD((it + 2) * 32);
        mma_block64(smem[cur], smem[cur] + 2560, mw, nw, g, tig, acc);
        __syncthreads();
    }

    // ---- epilogue (smem reuse) ----
    float* red  = (float*)smem;
    float* cmax = red + 2048;
    float* cinv = cmax + 128;

    if (m0 < 256) {
        const int slot = (wid >> 1) * 4 + tig;
#pragma unroll
        for (int i = 0; i < 4; ++i) {
            int r0 = mw + i * 16 + g;
            float b0 = g_bf[m0 + r0], b1 = g_bf[m0 + r0 + 8];
            float p0 = 0.f, p1 = 0.f;
#pragma unroll
            for (int j = 0; j < 8; ++j) {
                int col = s0 + nw + j * 8 + tig * 2;
                float e0 = __expf(acc[i][j][0] + b0), e1 = __expf(acc[i][j][1] + b0);
                float e2 = __expf(acc[i][j][2] + b1), e3 = __expf(acc[i][j][3] + b1);
                __half* o0 = g_k + (size_t)(b * CCH + m0 + r0) * SPA + col;
                *(uint32_t*)o0 = pk2(e0, e1);
                *(uint32_t*)(o0 + (size_t)8 * SPA) = pk2(e2, e3);
                p0 += e0 + e1;
                p1 += e2 + e3;
            }
            red[r0 * 8 + slot]       = p0;
            red[(r0 + 8) * 8 + slot] = p1;
        }
        __syncthreads();
        {
            float s = 0.f;
#pragma unroll
            for (int t = 0; t < 8; ++t) s += red[tid * 8 + t];
            g_kpart[(size_t)(by & 127) * 2048 + (b * 256 + m0 + tid)] = s;
        }
    } else if (m0 < 512) {
        const int rbase = m0 - 256;
        const int slotq = (wid & 1) * 8 + g;
#pragma unroll
        for (int j = 0; j < 8; ++j) {
            int cl = nw + j * 8 + tig * 2;
            float mA = -1e30f, mB = -1e30f;
#pragma unroll
            for (int i = 0; i < 4; ++i) {
                float b0 = g_bf[m0 + mw + i * 16 + g];
                float b1 = g_bf[m0 + mw + i * 16 + g + 8];
                mA = fmaxf(mA, fmaxf(acc[i][j][0] + b0, acc[i][j][2] + b1));
                mB = fmaxf(mB, fmaxf(acc[i][j][1] + b0, acc[i][j][3] + b1));
            }
            red[cl * 16 + slotq]       = mA;
            red[(cl + 1) * 16 + slotq] = mB;
        }
        __syncthreads();
        {
            float m = -1e30f;
#pragma unroll
            for (int t = 0; t < 16; ++t) m = fmaxf(m, red[tid * 16 + t]);
            cmax[tid] = m;
        }
        __syncthreads();
#pragma unroll
        for (int j = 0; j < 8; ++j) {
            int cl = nw + j * 8 + tig * 2;
            float cmA = cmax[cl], cmB = cmax[cl + 1];
            float sA = 0.f, sB = 0.f;
#pragma unroll
            for (int i = 0; i < 4; ++i) {
                float b0 = g_bf[m0 + mw + i * 16 + g];
                float b1 = g_bf[m0 + mw + i * 16 + g + 8];
                sA += __expf(acc[i][j][0] + b0 - cmA) + __expf(acc[i][j][2] + b1 - cmA);
                sB += __expf(acc[i][j][1] + b0 - cmB) + __expf(acc[i][j][3] + b1 - cmB);
            }
            red[cl * 16 + slotq]       = sA;
            red[(cl + 1) * 16 + slotq] = sB;
        }
        __syncthreads();
        {
            float s = 0.f;
#pragma unroll
            for (int t = 0; t < 16; ++t) s += red[tid * 16 + t];
            cinv[tid] = 1.f / s;
        }
        __syncthreads();
#pragma unroll
        for (int i = 0; i < 4; ++i) {
            int r0 = mw + i * 16 + g;
            float b0 = g_bf[m0 + r0], b1 = g_bf[m0 + r0 + 8];
#pragma unroll
            for (int j = 0; j < 8; ++j) {
                int cl = nw + j * 8 + tig * 2;
                float cmA = cmax[cl], cmB = cmax[cl + 1];
                float ciA = cinv[cl], ciB = cinv[cl + 1];
                int col = s0 + cl;
                __half* o0 = g_q + (size_t)(b * CCH + rbase + r0) * SPA + col;
                *(uint32_t*)o0 = pk2(__expf(acc[i][j][0] + b0 - cmA) * ciA,
                                     __expf(acc[i][j][1] + b0 - cmB) * ciB);
                *(uint32_t*)(o0 + (size_t)8 * SPA) =
                    pk2(__expf(acc[i][j][2] + b1 - cmA) * ciA,
                        __expf(acc[i][j][3] + b1 - cmB) * ciB);
            }
        }
    } else {
        const int rbase = m0 - 512;
#pragma unroll
        for (int i = 0; i < 4; ++i) {
            int r0 = mw + i * 16 + g;
            float b0 = g_bf[m0 + r0], b1 = g_bf[m0 + r0 + 8];
#pragma unroll
            for (int j = 0; j < 8; ++j) {
                int col = s0 + nw + j * 8 + tig * 2;
                __half* o0 = g_v + (size_t)(b * CCH + rbase + r0) * SPA + col;
                *(uint32_t*)o0 = pk2(acc[i][j][0] + b0, acc[i][j][1] + b0);
                *(uint32_t*)(o0 + (size_t)8 * SPA) = pk2(acc[i][j][2] + b1, acc[i][j][3] + b1);
            }
        }
    }
}

// ---------------- K4: reduce k partial sums -> 1/sum ----------------
__global__ void k_ksum() {
    int row = blockIdx.x * 256 + threadIdx.x;
    float s = 0.f;
    for (int st = 0; st < 128; ++st) s += g_kpart[(size_t)st * 2048 + row];
    g_kinv[row] = 1.f / s;
}

// ---------------- K6: context — R15 proven (64x32, 256 threads) ----------------
__global__ __launch_bounds__(256) void k_context() {
    __shared__ uint32_t As[2][128 * AS_H];
    __shared__ uint32_t Bs[2][16 * BS_H];
    const int tid = threadIdx.x;
    const int lane = tid & 31, wid = tid >> 5;
    const int g = lane >> 2, tig = lane & 3;
    const int mw = (wid & 1) * 64, nw = (wid >> 1) * 32;

    const int split = blockIdx.x;
    const int bn = blockIdx.y;
    const __half* Kb = g_k + ((size_t)bn * HK) * SPA;
    const __half* Vb = g_v + ((size_t)bn * HK) * SPA;
    const int sb0 = split * 1024;

    const int row = tid >> 1, sq = (tid & 1) * 16;
    const float kivs = g_kinv[bn * HK + row] * CTX_SCALE;
    const uint32_t kiv2 = pk2(kivs, kivs);

    uint4 ra0, ra1, rb0, rb1;
    float acc[4][4][4] = {};

#define CTX_LOAD(ks) do { \
    const uint4* ksrc = (const uint4*)(Kb + (size_t)row * SPA + (ks) + sq); \
    ra0 = ksrc[0]; ra1 = ksrc[1]; \
    const uint4* vsrc = (const uint4*)(Vb + (size_t)row * SPA + (ks) + sq); \
    rb0 = vsrc[0]; rb1 = vsrc[1]; \
} while (0)

#define CTX_STAGE(buf) do { \
    uint32_t* dA = As[buf] + row * AS_H + (sq >> 1); \
    dA[0] = hmul2(ra0.x, kiv2); dA[1] = hmul2(ra0.y, kiv2); \
    dA[2] = hmul2(ra0.z, kiv2); dA[3] = hmul2(ra0.w, kiv2); \
    dA[4] = hmul2(ra1.x, kiv2); dA[5] = hmul2(ra1.y, kiv2); \
    dA[6] = hmul2(ra1.z, kiv2); dA[7] = hmul2(ra1.w, kiv2); \
    const int rbo = sq >> 1; \
    uint32_t* BB = Bs[buf]; \
    BB[(rbo + 0) * BS_H + row] = rb0.x; BB[(rbo + 1) * BS_H + row] = rb0.y; \
    BB[(rbo + 2) * BS_H + row] = rb0.z; BB[(rbo + 3) * BS_H + row] = rb0.w; \
    BB[(rbo + 4) * BS_H + row] = rb1.x; BB[(rbo + 5) * BS_H + row] = rb1.y; \
    BB[(rbo + 6) * BS_H + row] = rb1.z; BB[(rbo + 7) * BS_H + row] = rb1.w; \
} while (0)

    CTX_LOAD(sb0);
    CTX_STAGE(0);
    CTX_LOAD(sb0 + 32);
    __syncthreads();

    for (int it = 0; it < 32; ++it) {
        const int cur = it & 1;
        if (it + 1 < 32) CTX_STAGE(cur ^ 1);
        if (it + 2 < 32) CTX_LOAD(sb0 + (it + 2) * 32);
        mma_block16(As[cur], Bs[cur], mw, nw, g, tig, acc);
        __syncthreads();
    }

    float* outp = g_ctx_part + ((size_t)(bn * 16 + split)) * 16384;
#pragma unroll
    for (int i = 0; i < 4; ++i) {
        int row0 = mw + i * 16 + g;
#pragma unroll
        for (int j = 0; j < 4; ++j) {
            int col = nw + j * 8 + tig * 2;
            float* o0 = outp + row0 * 128 + col;
            float* o1 = o0 + 8 * 128;
            *(float2*)o0 = make_float2(acc[i][j][0] * CTX_UNSCALE, acc[i][j][1] * CTX_UNSCALE);
            *(float2*)o1 = make_float2(acc[i][j][2] * CTX_UNSCALE, acc[i][j][3] * CTX_UNSCALE);
        }
    }
}

// ---------------- K7: reduce partials + pooled partials ----------------
__global__ void k_reduce_ctx() {
    const int ch = blockIdx.x;
    const int bn = blockIdx.y;
    const int tid = threadIdx.x;
    const int e0 = ch * 2048;
    float acc = 0.f;
    for (int e = e0 + tid; e < e0 + 2048; e += 256) {
        float s = 0.f;
#pragma unroll
        for (int p = 0; p < 16; ++p)
            s += g_ctx_part[((size_t)(bn * 16 + p)) * 16384 + e];
        g_context[((size_t)bn << 14) + e] = s;
        acc += s;
    }
    __shared__ float sm[256];
    sm[tid] = acc; __syncthreads();
    for (int st = 128; st > 0; st >>= 1) {
        if (tid < st) sm[tid] += sm[tid + st];
        __syncthreads();
    }
    if (tid == 0) g_pooled_part[bn * 8 + ch] = sm[0];
}

// ---------------- K8: SE gate ----------------
__global__ void k_gate(const float* __restrict__ w_fc1, const float* __restrict__ b_fc1,
                       const float* __restrict__ w_fc2, const float* __restrict__ b_fc2) {
    int b = threadIdx.x;
    if (b >= BATCH) return;
    float p0 = 0.f, p1 = 0.f;
#pragma unroll
    for (int ch = 0; ch < 8; ++ch) {
        p0 += g_pooled_part[(b * 2) * 8 + ch];
        p1 += g_pooled_part[(b * 2 + 1) * 8 + ch];
    }
    p0 *= (1.f / 16384.f);
    p1 *= (1.f / 16384.f);
    float h0 = fmaxf(0.f, p0 * w_fc1[0] + p1 * w_fc1[1] + b_fc1[0]);
    float h1 = fmaxf(0.f, p0 * w_fc1[2] + p1 * w_fc1[3] + b_fc1[1]);
    float z0 = h0 * w_fc2[0] + h1 * w_fc2[1] + b_fc2[0];
    float z1 = h0 * w_fc2[2] + h1 * w_fc2[3] + b_fc2[1];
    g_gate[b * 2]     = 1.f / (1.f + __expf(-z0));
    g_gate[b * 2 + 1] = 1.f / (1.f + __expf(-z1));
}

// ---------------- K10: M_b = w_rep-slices @ (gated combined ctx_b), fp16 out ----
__global__ __launch_bounds__(256) void k_mkM(const float* __restrict__ w_rep,
                                             const float* __restrict__ w_se) {
    __shared__ float Ws[64][65];
    __shared__ float Cs[64][65];
    const int bid = blockIdx.x;
    const int b = bid >> 4;
    const int rem = bid & 15;
    const int ot = rem >> 2, kt = rem & 3;
    const int n = kt >> 1;
    const int kc0 = (kt & 1) << 6;
    const int o0 = ot << 6;
    const int tid = threadIdx.x;
    const int tx = tid & 15, ty = tid >> 4;
    const float* ctx0 = g_context + ((size_t)(b * 2) << 14);
    const float* ctx1 = g_context + ((size_t)(b * 2 + 1) << 14);
    const float wg0 = w_se[0] * g_gate[b * 2];
    const float wg1 = w_se[1] * g_gate[b * 2 + 1];
    float acc[4][4] = {};
    const int lrow = tid >> 2;
    const int lc0 = (tid & 3) << 4;
    for (int h = 0; h < 2; ++h) {
        const int vb = n * 128 + h * 64;
#pragma unroll
        for (int f = 0; f < 4; ++f) {
            float4 wv = *(const float4*)(w_rep + (o0 + lrow) * 256 + vb + lc0 + f * 4);
            Ws[lrow][lc0 + f * 4 + 0] = wv.x; Ws[lrow][lc0 + f * 4 + 1] = wv.y;
            Ws[lrow][lc0 + f * 4 + 2] = wv.z; Ws[lrow][lc0 + f * 4 + 3] = wv.w;
            int cidx = (kc0 + lrow) * 128 + h * 64 + lc0 + f * 4;
            float4 c0 = *(const float4*)(ctx0 + cidx);
            float4 c1 = *(const float4*)(ctx1 + cidx);
            Cs[lrow][lc0 + f * 4 + 0] = wg0 * c0.x + wg1 * c1.x;
            Cs[lrow][lc0 + f * 4 + 1] = wg0 * c0.y + wg1 * c1.y;
            Cs[lrow][lc0 + f * 4 + 2] = wg0 * c0.z + wg1 * c1.z;
            Cs[lrow][lc0 + f * 4 + 3] = wg0 * c0.w + wg1 * c1.w;
        }
        __syncthreads();
        for (int vl = 0; vl < 64; ++vl) {
            float a[4], bb[4];
#pragma unroll
            for (int i = 0; i < 4; ++i) a[i]  = Ws[ty * 4 + i][vl];
#pragma unroll
            for (int j = 0; j < 4; ++j) bb[j] = Cs[tx * 4 + j][vl];
#pragma unroll
            for (int i = 0; i < 4; ++i)
#pragma unroll
                for (int j = 0; j < 4; ++j) acc[i][j] += a[i] * bb[j];
        }
        __syncthreads();
    }
#pragma unroll
    for (int i = 0; i < 4; ++i)
#pragma unroll
        for (int j = 0; j < 4; ++j)
            g_M_h[(size_t)b * 65536 + (o0 + ty * 4 + i) * 256 + kt * 64 + tx * 4 + j] =
                __float2half(acc[i][j]);
}

// ---------------- K11: b2 bias fold ----------------
__global__ void k_bias2(const float* __restrict__ w_rep, const float* __restrict__ b_rep,
                        const float* __restrict__ b_se) {
    int o = threadIdx.x;
    float s = 0.f;
    for (int c = 0; c < 256; ++c) s += w_rep[o * 256 + c];
    g_b2[o] = b_rep[o] + b_se[0] * s;
}

// ---------------- K12: final GEMM (R12 proven) ----------------
__global__ __launch_bounds__(256) void k_final_fused(float* __restrict__ out) {
    __shared__ uint32_t As[2][128 * AS_H];
    __shared__ uint32_t Bs[2][16 * BS_H];
    const int tid = threadIdx.x;
    const int lane = tid & 31, wid = tid >> 5;
    const int g = lane >> 2, tig = lane & 3;
    const int mw = (wid & 1) * 64, nw = (wid >> 1) * 32;

    const int m0 = blockIdx.x << 7;
    const int by = blockIdx.y;
    const int b = by >> 7, s0 = (by & 127) << 7;
    const __half* Am = g_M_h + (size_t)b * 65536;
    const __half* Bq = g_q + (size_t)b * CCH * SPA;

    const int ar = tid >> 1, ak = (tid & 1) * 16;
    const int bkp = tid >> 4, bs = (tid & 15) * 8;

    uint4 pa0, pa1, rb0, rb1;
    float acc[4][4][4] = {};

#define FIN_LOAD(ks) do { \
    const uint4* ap = (const uint4*)(Am + (size_t)(m0 + ar) * 256 + (ks) + ak); \
    pa0 = ap[0]; pa1 = ap[1]; \
    const __half* q0_ = Bq + (size_t)((ks) + 2 * bkp) * SPA + s0 + bs; \
    rb0 = *(const uint4*)q0_; \
    rb1 = *(const uint4*)(q0_ + SPA); \
} while (0)

#define FIN_STAGE(buf) do { \
    uint32_t* dA = As[buf] + ar * AS_H + (ak >> 1); \
    *(uint4*)(dA + 0) = pa0; *(uint4*)(dA + 4) = pa1; \
    const uint32_t* w0 = (const uint32_t*)&rb0; \
    const uint32_t* w1 = (const uint32_t*)&rb1; \
    uint32_t* dB = Bs[buf] + bkp * BS_H + bs; \
    _Pragma("unroll") \
    for (int q = 0; q < 4; ++q) { \
        dB[2 * q]     = prmt(w0[q], w1[q], 0x5410); \
        dB[2 * q + 1] = prmt(w0[q], w1[q], 0x7632); \
    } \
} while (0)

    FIN_LOAD(0);
    FIN_STAGE(0);
    FIN_LOAD(32);
    __syncthreads();

    for (int it = 0; it < 8; ++it) {
        const int cur = it & 1;
        if (it + 1 < 8) FIN_STAGE(cur ^ 1);
        if (it + 2 < 8) FIN_LOAD((it + 2) * 32);
        mma_block16(As[cur], Bs[cur], mw, nw, g, tig, acc);
        __syncthreads();
    }

#pragma unroll
    for (int i = 0; i < 4; ++i) {
        int row0 = m0 + mw + i * 16 + g;
        float bias0 = g_b2[row0];
        float bias1 = g_b2[row0 + 8];
#pragma unroll
        for (int j = 0; j < 4; ++j) {
            int col = s0 + nw + j * 8 + tig * 2;
            float* o0 = out + (size_t)(b * CCH + row0) * SPA + col;
            float* o1 = o0 + (size_t)8 * SPA;
            *(float2*)o0 = make_float2(acc[i][j][0] + bias0, acc[i][j][1] + bias0);
            *(float2*)o1 = make_float2(acc[i][j][2] + bias1, acc[i][j][3] + bias1);
        }
    }
}

// ---------------- launch ----------------
extern "C" void kernel_launch(void* const* d_in, const int* in_sizes, int n_in,
                              void* d_out, int out_size) {
    const float* x     = (const float*)d_in[0];
    const float* gamma = (const float*)d_in[1];
    const float* beta  = (const float*)d_in[2];
    const float* wk    = (const float*)d_in[3];
    const float* bk    = (const float*)d_in[4];
    const float* wq    = (const float*)d_in[5];
    const float* bq    = (const float*)d_in[6];
    const float* wv    = (const float*)d_in[7];
    const float* bv    = (const float*)d_in[8];
    const float* w_fc1 = (const float*)d_in[9];
    const float* b_fc1 = (const float*)d_in[10];
    const float* w_fc2 = (const float*)d_in[11];
    const float* b_fc2 = (const float*)d_in[12];
    const float* w_se  = (const float*)d_in[13];
    const float* b_se  = (const float*)d_in[14];
    const float* w_rep = (const float*)d_in[15];
    const float* b_rep = (const float*)d_in[16];
    float* out = (float*)d_out;

    k_bnstats_part<<<dim3(8, 128), 256>>>(x);
    k_bnstats_final<<<1, 256>>>();
    k_fuseW<<<3, 256>>>(wk, bk, wq, bq, wv, bv, gamma, beta);
    k_gemm_kqv<<<dim3(6, 1024), 128>>>();
    k_ksum<<<8, 256>>>();
    k_context<<<dim3(16, 16), 256>>>();
    k_reduce_ctx<<<dim3(8, 16), 256>>>();
    k_gate<<<1, 32>>>(w_fc1, b_fc1, w_fc2, b_fc2);
    k_mkM<<<128, 256>>>(w_rep, w_se);
    k_bias2<<<1, 256>>>(w_rep, b_rep, b_se);
    k_final_fused<<<dim3(2, 1024), 256>>>(out);
}